// round 1
// baseline (speedup 1.0000x reference)
#include <cuda_runtime.h>
#include <math.h>

#define NTPAIR 250000
#define NNODE  20000
#define RPROJ  8
#define EMBD   64
#define NRELS  64
#define NCLS   16
#define NRP    (NNODE * RPROJ)

// -------- scratch (no allocations allowed) --------
__device__ float g_l1[NTPAIR * RPROJ];      // raw l1 coefs  [pair][r]
__device__ float g_l2[NTPAIR * RPROJ];      // softmax l2    [pair][r]
__device__ float g_colsum[NRP];             // -> reciprocal after k1b
__device__ float g_rowsum[NRP];             // -> 1/max(.,1e-6) after k1b
__device__ float g_h[NNODE * EMBD];         // layer-1 hidden (pre relu/bias)
__device__ float g_g[NNODE * RPROJ * NCLS]; // g[n][r'][c] = relu(h+b1)[n] . W2[r']

// ==================== K0: init ====================
__global__ void k0_init(float* __restrict__ out, const float* __restrict__ bias2) {
    int i = blockIdx.x * blockDim.x + threadIdx.x;
    int stride = gridDim.x * blockDim.x;
    for (int j = i; j < NRP; j += stride) { g_colsum[j] = 0.f; g_rowsum[j] = 0.f; }
    for (int j = i; j < NNODE * EMBD; j += stride) g_h[j] = 0.f;
    for (int j = i; j < NNODE * NCLS; j += stride) out[j] = __ldg(&bias2[j & 15]);
}

// ==================== K1: coefficients ====================
// l1 = rel @ W_l1 + b1 ; l2 = softmax(rel @ W_l2 + b2)
// + accumulate colsum[o*r] (of l1) and rowsum[s*r] (of l2).
// r=0 collapses to index 0 for ALL pairs -> block-reduce + single atomic.
__global__ void __launch_bounds__(128) k1_coeff(
    const float* __restrict__ rel, const int* __restrict__ hrow,
    const int* __restrict__ vcol,
    const float* __restrict__ Wl1, const float* __restrict__ bl1,
    const float* __restrict__ Wl2, const float* __restrict__ bl2)
{
    __shared__ float Wt1[RPROJ * NRELS];   // [r][k]
    __shared__ float Wt2[RPROJ * NRELS];
    __shared__ float sred[128];
    int tid = threadIdx.x;
    for (int i = tid; i < NRELS * RPROJ; i += 128) {
        int k = i >> 3, r = i & 7;
        Wt1[r * NRELS + k] = Wl1[i];
        Wt2[r * NRELS + k] = Wl2[i];
    }
    __syncthreads();

    int base = blockIdx.x * 256;
    float csum0 = 0.f, rsum0 = 0.f;

    #pragma unroll
    for (int half = 0; half < 2; half++) {
        int p = base + half * 128 + tid;
        if (p < NTPAIR) {
            float a1[8], a2[8];
            #pragma unroll
            for (int r = 0; r < 8; r++) { a1[r] = __ldg(&bl1[r]); a2[r] = __ldg(&bl2[r]); }

            const float4* rp4 = (const float4*)(rel + (size_t)p * 64);
            #pragma unroll
            for (int k4 = 0; k4 < 16; k4++) {
                float4 x = __ldg(&rp4[k4]);
                #pragma unroll
                for (int r = 0; r < 8; r++) {
                    float4 w1 = *(const float4*)&Wt1[r * 64 + k4 * 4];
                    a1[r] += x.x * w1.x + x.y * w1.y + x.z * w1.z + x.w * w1.w;
                    float4 w2 = *(const float4*)&Wt2[r * 64 + k4 * 4];
                    a2[r] += x.x * w2.x + x.y * w2.y + x.z * w2.z + x.w * w2.w;
                }
            }
            // softmax over the 8 values of a2
            float m = a2[0];
            #pragma unroll
            for (int r = 1; r < 8; r++) m = fmaxf(m, a2[r]);
            float ssum = 0.f;
            #pragma unroll
            for (int r = 0; r < 8; r++) { a2[r] = expf(a2[r] - m); ssum += a2[r]; }
            float inv = 1.f / ssum;
            #pragma unroll
            for (int r = 0; r < 8; r++) a2[r] *= inv;

            float4* o1 = (float4*)&g_l1[(size_t)p * 8];
            o1[0] = make_float4(a1[0], a1[1], a1[2], a1[3]);
            o1[1] = make_float4(a1[4], a1[5], a1[6], a1[7]);
            float4* o2 = (float4*)&g_l2[(size_t)p * 8];
            o2[0] = make_float4(a2[0], a2[1], a2[2], a2[3]);
            o2[1] = make_float4(a2[4], a2[5], a2[6], a2[7]);

            int s = __ldg(&hrow[p]);
            int o = __ldg(&vcol[p]);
            csum0 += a1[0];
            rsum0 += a2[0];
            #pragma unroll
            for (int r = 1; r < 8; r++) {
                atomicAdd(&g_colsum[o * r], a1[r]);
                atomicAdd(&g_rowsum[s * r], a2[r]);
            }
        }
    }

    // block reduction for the r=0 hot index
    sred[tid] = csum0; __syncthreads();
    for (int st = 64; st > 0; st >>= 1) { if (tid < st) sred[tid] += sred[tid + st]; __syncthreads(); }
    if (tid == 0) atomicAdd(&g_colsum[0], sred[0]);
    __syncthreads();
    sred[tid] = rsum0; __syncthreads();
    for (int st = 64; st > 0; st >>= 1) { if (tid < st) sred[tid] += sred[tid + st]; __syncthreads(); }
    if (tid == 0) atomicAdd(&g_rowsum[0], sred[0]);
}

// ==================== K1b: reciprocals ====================
__global__ void k1b_recip() {
    int i = blockIdx.x * blockDim.x + threadIdx.x;
    int stride = gridDim.x * blockDim.x;
    for (int j = i; j < NRP; j += stride) {
        g_colsum[j] = 1.0f / g_colsum[j];
        g_rowsum[j] = 1.0f / fmaxf(g_rowsum[j], 1e-6f);
    }
}

// ==================== K2: layer-1 aggregation ====================
// h[s] += sum_r (l1[p][r] * csuminv[o*r]) * W1flat[o*r]
// warp handles 128 consecutive pairs; pairs are sorted by s -> register
// accumulator per s-run, flushed once per run via atomics.
// lane: cl = lane&15 owns 4 emb cols; rb = lane>>4 picks even/odd r.
__global__ void __launch_bounds__(256) k2_layer1(
    const int* __restrict__ hrow, const int* __restrict__ vcol,
    const float* __restrict__ W1)
{
    int warp = (blockIdx.x * blockDim.x + threadIdx.x) >> 5;
    int lane = threadIdx.x & 31;
    int p0 = warp * 128;
    if (p0 >= NTPAIR) return;
    int pend = min(p0 + 128, NTPAIR);
    int cl = lane & 15, rb = lane >> 4;

    float4 acc = make_float4(0.f, 0.f, 0.f, 0.f);
    int cur_s = -1;

    for (int p = p0; p < pend; p++) {
        int s = __ldg(&hrow[p]);
        if (s != cur_s) {
            if (cur_s >= 0) {
                acc.x += __shfl_xor_sync(0xffffffffu, acc.x, 16);
                acc.y += __shfl_xor_sync(0xffffffffu, acc.y, 16);
                acc.z += __shfl_xor_sync(0xffffffffu, acc.z, 16);
                acc.w += __shfl_xor_sync(0xffffffffu, acc.w, 16);
                if (rb == 0) {
                    float* hp = &g_h[cur_s * 64 + cl * 4];
                    atomicAdd(hp + 0, acc.x);
                    atomicAdd(hp + 1, acc.y);
                    atomicAdd(hp + 2, acc.z);
                    atomicAdd(hp + 3, acc.w);
                }
                acc = make_float4(0.f, 0.f, 0.f, 0.f);
            }
            cur_s = s;
        }
        int o = __ldg(&vcol[p]);
        int rl = lane & 7;
        float cf = __ldg(&g_l1[(size_t)p * 8 + rl]) * __ldg(&g_colsum[o * rl]);
        #pragma unroll
        for (int j = 0; j < 4; j++) {
            int r = 2 * j + rb;
            float coef = __shfl_sync(0xffffffffu, cf, r);
            float4 w = __ldg((const float4*)&W1[(size_t)(o * r) * 64] + cl);
            acc.x += coef * w.x;
            acc.y += coef * w.y;
            acc.z += coef * w.z;
            acc.w += coef * w.w;
        }
    }
    if (cur_s >= 0) {
        acc.x += __shfl_xor_sync(0xffffffffu, acc.x, 16);
        acc.y += __shfl_xor_sync(0xffffffffu, acc.y, 16);
        acc.z += __shfl_xor_sync(0xffffffffu, acc.z, 16);
        acc.w += __shfl_xor_sync(0xffffffffu, acc.w, 16);
        if (rb == 0) {
            float* hp = &g_h[cur_s * 64 + cl * 4];
            atomicAdd(hp + 0, acc.x);
            atomicAdd(hp + 1, acc.y);
            atomicAdd(hp + 2, acc.z);
            atomicAdd(hp + 3, acc.w);
        }
    }
}

// ==================== K3: relu(h+b1) and g = h @ W2 (per r') ====================
// block handles 128 nodes; warp w handles r' = w; lane owns 4 nodes x 16 classes.
__global__ void __launch_bounds__(256) k3_relu_g(
    const float* __restrict__ bias1, const float* __restrict__ W2)
{
    __shared__ float sh[128 * 65];
    int tid = threadIdx.x;
    int nbase = blockIdx.x * 128;
    for (int i = tid; i < 128 * 64; i += 256) {
        int n = i >> 6, c = i & 63;
        float v = 0.f;
        if (nbase + n < NNODE)
            v = fmaxf(g_h[(nbase + n) * 64 + c] + __ldg(&bias1[c]), 0.f);
        sh[n * 65 + c] = v;
    }
    __syncthreads();

    int rp = tid >> 5;      // warp id = r'
    int lane = tid & 31;
    float acc[4][16];
    #pragma unroll
    for (int j = 0; j < 4; j++)
        #pragma unroll
        for (int c = 0; c < 16; c++) acc[j][c] = 0.f;

    for (int k = 0; k < 64; k++) {
        const float4* wrow = (const float4*)&W2[(rp * 64 + k) * 16];
        float4 wa = __ldg(wrow + 0);
        float4 wb = __ldg(wrow + 1);
        float4 wc = __ldg(wrow + 2);
        float4 wd = __ldg(wrow + 3);
        #pragma unroll
        for (int j = 0; j < 4; j++) {
            float x = sh[(lane + 32 * j) * 65 + k];
            acc[j][0]  += x * wa.x; acc[j][1]  += x * wa.y; acc[j][2]  += x * wa.z; acc[j][3]  += x * wa.w;
            acc[j][4]  += x * wb.x; acc[j][5]  += x * wb.y; acc[j][6]  += x * wb.z; acc[j][7]  += x * wb.w;
            acc[j][8]  += x * wc.x; acc[j][9]  += x * wc.y; acc[j][10] += x * wc.z; acc[j][11] += x * wc.w;
            acc[j][12] += x * wd.x; acc[j][13] += x * wd.y; acc[j][14] += x * wd.z; acc[j][15] += x * wd.w;
        }
    }
    #pragma unroll
    for (int j = 0; j < 4; j++) {
        int n = nbase + lane + 32 * j;
        if (n < NNODE) {
            float4* gp = (float4*)&g_g[(size_t)n * 128 + rp * 16];
            gp[0] = make_float4(acc[j][0],  acc[j][1],  acc[j][2],  acc[j][3]);
            gp[1] = make_float4(acc[j][4],  acc[j][5],  acc[j][6],  acc[j][7]);
            gp[2] = make_float4(acc[j][8],  acc[j][9],  acc[j][10], acc[j][11]);
            gp[3] = make_float4(acc[j][12], acc[j][13], acc[j][14], acc[j][15]);
        }
    }
}

// ==================== K4: layer-2 + final einsum (fused) ====================
// logits[(s*r)%20000][c] += (l2[p][r]*rsuminv[s*r]) * g[o][(s*r)/20000][c]
// lane: cl = lane&15 owns class c; rb = lane>>4; lane covers r in {rb, rb+2, rb+4, rb+6}.
__global__ void __launch_bounds__(256) k4_layer2(
    const int* __restrict__ hrow, const int* __restrict__ vcol,
    float* __restrict__ out)
{
    int warp = (blockIdx.x * blockDim.x + threadIdx.x) >> 5;
    int lane = threadIdx.x & 31;
    int p0 = warp * 128;
    if (p0 >= NTPAIR) return;
    int pend = min(p0 + 128, NTPAIR);
    int cl = lane & 15, rb = lane >> 4;

    float acc[4] = {0.f, 0.f, 0.f, 0.f};
    int np[4], gofs[4];
    int cur_s = -1;

    for (int p = p0; p < pend; p++) {
        int s = __ldg(&hrow[p]);
        if (s != cur_s) {
            if (cur_s >= 0) {
                #pragma unroll
                for (int j = 0; j < 4; j++) {
                    atomicAdd(&out[np[j] * 16 + cl], acc[j]);
                    acc[j] = 0.f;
                }
            }
            cur_s = s;
            #pragma unroll
            for (int j = 0; j < 4; j++) {
                int r = 2 * j + rb;
                int v = s * r;
                int rprime = v / 20000;
                np[j] = v - rprime * 20000;
                gofs[j] = rprime * 16 + cl;
            }
        }
        int o = __ldg(&vcol[p]);
        int rl = lane & 7;
        float cf = __ldg(&g_l2[(size_t)p * 8 + rl]) * __ldg(&g_rowsum[s * rl]);
        const float* gbase = &g_g[(size_t)o * 128];
        #pragma unroll
        for (int j = 0; j < 4; j++) {
            float coef = __shfl_sync(0xffffffffu, cf, 2 * j + rb);
            acc[j] += coef * __ldg(&gbase[gofs[j]]);
        }
    }
    if (cur_s >= 0) {
        #pragma unroll
        for (int j = 0; j < 4; j++)
            atomicAdd(&out[np[j] * 16 + cl], acc[j]);
    }
}

// ==================== launch ====================
extern "C" void kernel_launch(void* const* d_in, const int* in_sizes, int n_in,
                              void* d_out, int out_size) {
    (void)in_sizes; (void)n_in; (void)out_size;
    const float* rel  = (const float*)d_in[0];
    const int*   hrow = (const int*)d_in[1];
    const int*   vcol = (const int*)d_in[4];
    const float* Wl1  = (const float*)d_in[5];
    const float* bl1  = (const float*)d_in[6];
    const float* Wl2  = (const float*)d_in[7];
    const float* bl2  = (const float*)d_in[8];
    const float* W1   = (const float*)d_in[9];
    const float* W2   = (const float*)d_in[10];
    const float* b1   = (const float*)d_in[11];
    const float* b2   = (const float*)d_in[12];
    float* out = (float*)d_out;

    k0_init<<<512, 256>>>(out, b2);
    k1_coeff<<<(NTPAIR + 255) / 256, 128>>>(rel, hrow, vcol, Wl1, bl1, Wl2, bl2);
    k1b_recip<<<(NRP + 255) / 256, 256>>>();
    {
        int nwarps = (NTPAIR + 127) / 128;
        int nblocks = (nwarps * 32 + 255) / 256;
        k2_layer1<<<nblocks, 256>>>(hrow, vcol, W1);
    }
    k3_relu_g<<<(NNODE + 127) / 128, 256>>>(b1, W2);
    {
        int nwarps = (NTPAIR + 127) / 128;
        int nblocks = (nwarps * 32 + 255) / 256;
        k4_layer2<<<nblocks, 256>>>(hrow, vcol, out);
    }
}

// round 3
// speedup vs baseline: 1.5650x; 1.5650x over previous
#include <cuda_runtime.h>
#include <math.h>

#define NTPAIR 250000
#define NNODE  20000
#define RPROJ  8
#define EMBD   64
#define NRELS  64
#define NCLS   16
#define NRP    (NNODE * RPROJ)

// -------- scratch (no allocations allowed) --------
__device__ float g_l1[NTPAIR * RPROJ];      // raw l1 coefs  [pair][r]
__device__ float g_l2[NTPAIR * RPROJ];      // softmax l2    [pair][r]
__device__ float g_colsum[NRP];             // -> reciprocal after k1b
__device__ float g_rowsum[NRP];             // -> 1/max(.,1e-6) reciprocal after k1b
__device__ float g_h[NNODE * EMBD];         // layer-1 hidden (pre relu/bias)
__device__ float g_g[NNODE * RPROJ * NCLS]; // g[n][r'][c] = relu(h+b1)[n] . W2[r']

// ==================== K0: init ====================
__global__ void k0_init(float* __restrict__ out, const float* __restrict__ bias2) {
    int i = blockIdx.x * blockDim.x + threadIdx.x;
    int stride = gridDim.x * blockDim.x;
    for (int j = i; j < NRP; j += stride) { g_colsum[j] = 0.f; g_rowsum[j] = 0.f; }
    for (int j = i; j < NNODE * EMBD; j += stride) g_h[j] = 0.f;
    for (int j = i; j < NNODE * NCLS; j += stride) out[j] = __ldg(&bias2[j & 15]);
}

// ==================== K1: coefficients ====================
// l1 = rel @ W_l1 + b1 ; l2 = softmax(rel @ W_l2 + b2)
// + accumulate colsum[o*r] (of l1) and rowsum[s*r] (of l2).
// r=0 collapses to index 0 for ALL pairs -> block-reduce + single atomic.
__global__ void __launch_bounds__(256) k1_coeff(
    const float* __restrict__ rel, const int* __restrict__ hrow,
    const int* __restrict__ vcol,
    const float* __restrict__ Wl1, const float* __restrict__ bl1,
    const float* __restrict__ Wl2, const float* __restrict__ bl2)
{
    __shared__ float Wt1[RPROJ * NRELS];   // [r][k]
    __shared__ float Wt2[RPROJ * NRELS];
    __shared__ float sred[256];
    int tid = threadIdx.x;
    for (int i = tid; i < NRELS * RPROJ; i += 256) {
        int k = i >> 3, r = i & 7;
        Wt1[r * NRELS + k] = Wl1[i];
        Wt2[r * NRELS + k] = Wl2[i];
    }
    __syncthreads();

    int p = blockIdx.x * 256 + tid;
    float csum0 = 0.f, rsum0 = 0.f;

    if (p < NTPAIR) {
        float a1[8], a2[8];
        #pragma unroll
        for (int r = 0; r < 8; r++) { a1[r] = __ldg(&bl1[r]); a2[r] = __ldg(&bl2[r]); }

        const float4* rp4 = (const float4*)(rel + (size_t)p * 64);
        #pragma unroll
        for (int k4 = 0; k4 < 16; k4++) {
            float4 x = __ldg(&rp4[k4]);
            #pragma unroll
            for (int r = 0; r < 8; r++) {
                float4 w1 = *(const float4*)&Wt1[r * 64 + k4 * 4];
                a1[r] += x.x * w1.x + x.y * w1.y + x.z * w1.z + x.w * w1.w;
                float4 w2 = *(const float4*)&Wt2[r * 64 + k4 * 4];
                a2[r] += x.x * w2.x + x.y * w2.y + x.z * w2.z + x.w * w2.w;
            }
        }
        // softmax over the 8 values of a2
        float m = a2[0];
        #pragma unroll
        for (int r = 1; r < 8; r++) m = fmaxf(m, a2[r]);
        float ssum = 0.f;
        #pragma unroll
        for (int r = 0; r < 8; r++) { a2[r] = expf(a2[r] - m); ssum += a2[r]; }
        float inv = 1.f / ssum;
        #pragma unroll
        for (int r = 0; r < 8; r++) a2[r] *= inv;

        float4* o1 = (float4*)&g_l1[(size_t)p * 8];
        o1[0] = make_float4(a1[0], a1[1], a1[2], a1[3]);
        o1[1] = make_float4(a1[4], a1[5], a1[6], a1[7]);
        float4* o2 = (float4*)&g_l2[(size_t)p * 8];
        o2[0] = make_float4(a2[0], a2[1], a2[2], a2[3]);
        o2[1] = make_float4(a2[4], a2[5], a2[6], a2[7]);

        int s = __ldg(&hrow[p]);
        int o = __ldg(&vcol[p]);
        csum0 = a1[0];
        rsum0 = a2[0];
        #pragma unroll
        for (int r = 1; r < 8; r++) {
            atomicAdd(&g_colsum[o * r], a1[r]);
            atomicAdd(&g_rowsum[s * r], a2[r]);
        }
    }

    // block reduction for the r=0 hot index
    sred[tid] = csum0; __syncthreads();
    for (int st = 128; st > 0; st >>= 1) { if (tid < st) sred[tid] += sred[tid + st]; __syncthreads(); }
    if (tid == 0) atomicAdd(&g_colsum[0], sred[0]);
    __syncthreads();
    sred[tid] = rsum0; __syncthreads();
    for (int st = 128; st > 0; st >>= 1) { if (tid < st) sred[tid] += sred[tid + st]; __syncthreads(); }
    if (tid == 0) atomicAdd(&g_rowsum[0], sred[0]);
}

// ==================== K1b: reciprocals ====================
__global__ void k1b_recip() {
    int i = blockIdx.x * blockDim.x + threadIdx.x;
    int stride = gridDim.x * blockDim.x;
    for (int j = i; j < NRP; j += stride) {
        g_colsum[j] = 1.0f / g_colsum[j];
        g_rowsum[j] = 1.0f / fmaxf(g_rowsum[j], 1e-6f);
    }
}

// ==================== K2: layer-1 aggregation ====================
// h[s] += sum_r (l1[p][r] * csuminv[o*r]) * W1flat[o*r]
// Warp handles 32 pairs. All index + coefficient loads are batched
// up-front into registers; the fully-unrolled main loop is shfl + gather only.
// cf[g] layout: lane = pgrp*8 + rmy holds coef of pair p0+g*4+pgrp, relation rmy.
__global__ void __launch_bounds__(256) k2_layer1(
    const int* __restrict__ hrow, const int* __restrict__ vcol,
    const float* __restrict__ W1)
{
    int warp = (blockIdx.x * blockDim.x + threadIdx.x) >> 5;
    int lane = threadIdx.x & 31;
    int p0 = warp * 32;
    if (p0 >= NTPAIR) return;
    int cnt = min(32, NTPAIR - p0);

    int s_l = 0, o_l = 0;
    if (lane < cnt) {
        s_l = __ldg(&hrow[p0 + lane]);
        o_l = __ldg(&vcol[p0 + lane]);
    }
    float inv0 = g_colsum[0];

    int rmy = lane & 7;      // relation owned for coefficient duty
    int pgrp = lane >> 3;    // pair-in-group owned (0..3)
    float cf[8];
    #pragma unroll
    for (int g = 0; g < 8; g++) {
        int pj = g * 4 + pgrp;
        int o = __shfl_sync(0xffffffffu, o_l, pj & 31);
        float v = 0.f;
        if (pj < cnt) {
            float l1v = __ldg(&g_l1[(size_t)(p0 + pj) * 8 + rmy]);
            float cs = (rmy == 0) ? inv0 : __ldg(&g_colsum[o * rmy]);
            v = l1v * cs;
        }
        cf[g] = v;
    }

    int cl = lane & 15, rb = lane >> 4;
    float4 acc = make_float4(0.f, 0.f, 0.f, 0.f);
    int cur_s = __shfl_sync(0xffffffffu, s_l, 0);

    #pragma unroll
    for (int j = 0; j < 32; j++) {
        if (j >= cnt) break;
        int s = __shfl_sync(0xffffffffu, s_l, j);
        int o = __shfl_sync(0xffffffffu, o_l, j);
        if (s != cur_s) {
            acc.x += __shfl_xor_sync(0xffffffffu, acc.x, 16);
            acc.y += __shfl_xor_sync(0xffffffffu, acc.y, 16);
            acc.z += __shfl_xor_sync(0xffffffffu, acc.z, 16);
            acc.w += __shfl_xor_sync(0xffffffffu, acc.w, 16);
            if (rb == 0) {
                float* hp = &g_h[cur_s * 64 + cl * 4];
                atomicAdd(hp + 0, acc.x);
                atomicAdd(hp + 1, acc.y);
                atomicAdd(hp + 2, acc.z);
                atomicAdd(hp + 3, acc.w);
            }
            acc = make_float4(0.f, 0.f, 0.f, 0.f);
            cur_s = s;
        }
        #pragma unroll
        for (int jj = 0; jj < 4; jj++) {
            int r = 2 * jj + rb;
            float coef = __shfl_sync(0xffffffffu, cf[j >> 2], (j & 3) * 8 + r);
            float4 w = __ldg((const float4*)&W1[(size_t)(o * r) * 64] + cl);
            acc.x += coef * w.x;
            acc.y += coef * w.y;
            acc.z += coef * w.z;
            acc.w += coef * w.w;
        }
    }
    acc.x += __shfl_xor_sync(0xffffffffu, acc.x, 16);
    acc.y += __shfl_xor_sync(0xffffffffu, acc.y, 16);
    acc.z += __shfl_xor_sync(0xffffffffu, acc.z, 16);
    acc.w += __shfl_xor_sync(0xffffffffu, acc.w, 16);
    if (rb == 0) {
        float* hp = &g_h[cur_s * 64 + cl * 4];
        atomicAdd(hp + 0, acc.x);
        atomicAdd(hp + 1, acc.y);
        atomicAdd(hp + 2, acc.z);
        atomicAdd(hp + 3, acc.w);
    }
}

// ==================== K3: relu(h+b1) and g = h @ W2 (per r') ====================
__global__ void __launch_bounds__(256) k3_relu_g(
    const float* __restrict__ bias1, const float* __restrict__ W2)
{
    __shared__ float sh[128 * 65];
    int tid = threadIdx.x;
    int nbase = blockIdx.x * 128;
    for (int i = tid; i < 128 * 64; i += 256) {
        int n = i >> 6, c = i & 63;
        float v = 0.f;
        if (nbase + n < NNODE)
            v = fmaxf(g_h[(nbase + n) * 64 + c] + __ldg(&bias1[c]), 0.f);
        sh[n * 65 + c] = v;
    }
    __syncthreads();

    int rp = tid >> 5;      // warp id = r'
    int lane = tid & 31;
    float acc[4][16];
    #pragma unroll
    for (int j = 0; j < 4; j++)
        #pragma unroll
        for (int c = 0; c < 16; c++) acc[j][c] = 0.f;

    for (int k = 0; k < 64; k++) {
        const float4* wrow = (const float4*)&W2[(rp * 64 + k) * 16];
        float4 wa = __ldg(wrow + 0);
        float4 wb = __ldg(wrow + 1);
        float4 wc = __ldg(wrow + 2);
        float4 wd = __ldg(wrow + 3);
        #pragma unroll
        for (int j = 0; j < 4; j++) {
            float x = sh[(lane + 32 * j) * 65 + k];
            acc[j][0]  += x * wa.x; acc[j][1]  += x * wa.y; acc[j][2]  += x * wa.z; acc[j][3]  += x * wa.w;
            acc[j][4]  += x * wb.x; acc[j][5]  += x * wb.y; acc[j][6]  += x * wb.z; acc[j][7]  += x * wb.w;
            acc[j][8]  += x * wc.x; acc[j][9]  += x * wc.y; acc[j][10] += x * wc.z; acc[j][11] += x * wc.w;
            acc[j][12] += x * wd.x; acc[j][13] += x * wd.y; acc[j][14] += x * wd.z; acc[j][15] += x * wd.w;
        }
    }
    #pragma unroll
    for (int j = 0; j < 4; j++) {
        int n = nbase + lane + 32 * j;
        if (n < NNODE) {
            float4* gp = (float4*)&g_g[(size_t)n * 128 + rp * 16];
            gp[0] = make_float4(acc[j][0],  acc[j][1],  acc[j][2],  acc[j][3]);
            gp[1] = make_float4(acc[j][4],  acc[j][5],  acc[j][6],  acc[j][7]);
            gp[2] = make_float4(acc[j][8],  acc[j][9],  acc[j][10], acc[j][11]);
            gp[3] = make_float4(acc[j][12], acc[j][13], acc[j][14], acc[j][15]);
        }
    }
}

// ==================== K4: layer-2 + final einsum (fused) ====================
// logits[(s*r)%20000][c] += (l2[p][r]*rsuminv[s*r]) * g[o][(s*r)/20000][c]
// Same batched-warp structure as K2. lane: cl = class, rb picks r parity.
__global__ void __launch_bounds__(256) k4_layer2(
    const int* __restrict__ hrow, const int* __restrict__ vcol,
    float* __restrict__ out)
{
    int warp = (blockIdx.x * blockDim.x + threadIdx.x) >> 5;
    int lane = threadIdx.x & 31;
    int p0 = warp * 32;
    if (p0 >= NTPAIR) return;
    int cnt = min(32, NTPAIR - p0);

    int s_l = 0, o_l = 0;
    if (lane < cnt) {
        s_l = __ldg(&hrow[p0 + lane]);
        o_l = __ldg(&vcol[p0 + lane]);
    }
    float inv0 = g_rowsum[0];

    int rmy = lane & 7;
    int pgrp = lane >> 3;
    float cf[8];
    #pragma unroll
    for (int g = 0; g < 8; g++) {
        int pj = g * 4 + pgrp;
        int s = __shfl_sync(0xffffffffu, s_l, pj & 31);
        float v = 0.f;
        if (pj < cnt) {
            float l2v = __ldg(&g_l2[(size_t)(p0 + pj) * 8 + rmy]);
            float rs = (rmy == 0) ? inv0 : __ldg(&g_rowsum[s * rmy]);
            v = l2v * rs;
        }
        cf[g] = v;
    }

    int cl = lane & 15, rb = lane >> 4;
    float acc[4] = {0.f, 0.f, 0.f, 0.f};
    int np[4], gofs[4];
    int cur_s = __shfl_sync(0xffffffffu, s_l, 0);
    #pragma unroll
    for (int jj = 0; jj < 4; jj++) {
        int r = 2 * jj + rb;
        int v = cur_s * r;
        int rprime = v / 20000;
        np[jj] = v - rprime * 20000;
        gofs[jj] = rprime * 16 + cl;
    }

    #pragma unroll
    for (int j = 0; j < 32; j++) {
        if (j >= cnt) break;
        int s = __shfl_sync(0xffffffffu, s_l, j);
        int o = __shfl_sync(0xffffffffu, o_l, j);
        if (s != cur_s) {
            #pragma unroll
            for (int jj = 0; jj < 4; jj++) {
                atomicAdd(&out[np[jj] * 16 + cl], acc[jj]);
                acc[jj] = 0.f;
            }
            cur_s = s;
            #pragma unroll
            for (int jj = 0; jj < 4; jj++) {
                int r = 2 * jj + rb;
                int v = s * r;
                int rprime = v / 20000;
                np[jj] = v - rprime * 20000;
                gofs[jj] = rprime * 16 + cl;
            }
        }
        const float* gb = &g_g[(size_t)o * 128];
        #pragma unroll
        for (int jj = 0; jj < 4; jj++) {
            int r = 2 * jj + rb;
            float coef = __shfl_sync(0xffffffffu, cf[j >> 2], (j & 3) * 8 + r);
            acc[jj] += coef * __ldg(&gb[gofs[jj]]);
        }
    }
    #pragma unroll
    for (int jj = 0; jj < 4; jj++)
        atomicAdd(&out[np[jj] * 16 + cl], acc[jj]);
}

// ==================== launch ====================
extern "C" void kernel_launch(void* const* d_in, const int* in_sizes, int n_in,
                              void* d_out, int out_size) {
    (void)in_sizes; (void)n_in; (void)out_size;
    const float* rel  = (const float*)d_in[0];
    const int*   hrow = (const int*)d_in[1];
    const int*   vcol = (const int*)d_in[4];
    const float* Wl1  = (const float*)d_in[5];
    const float* bl1  = (const float*)d_in[6];
    const float* Wl2  = (const float*)d_in[7];
    const float* bl2  = (const float*)d_in[8];
    const float* W1   = (const float*)d_in[9];
    const float* W2   = (const float*)d_in[10];
    const float* b1   = (const float*)d_in[11];
    const float* b2   = (const float*)d_in[12];
    float* out = (float*)d_out;

    k0_init<<<512, 256>>>(out, b2);
    k1_coeff<<<(NTPAIR + 255) / 256, 256>>>(rel, hrow, vcol, Wl1, bl1, Wl2, bl2);
    k1b_recip<<<(NRP + 255) / 256, 256>>>();
    {
        int nwarps = (NTPAIR + 31) / 32;
        int nblocks = (nwarps * 32 + 255) / 256;
        k2_layer1<<<nblocks, 256>>>(hrow, vcol, W1);
    }
    k3_relu_g<<<(NNODE + 127) / 128, 256>>>(b1, W2);
    {
        int nwarps = (NTPAIR + 31) / 32;
        int nblocks = (nwarps * 32 + 255) / 256;
        k4_layer2<<<nblocks, 256>>>(hrow, vcol, out);
    }
}